// round 6
// baseline (speedup 1.0000x reference)
#include <cuda_runtime.h>
#include <cstdint>

// Problem constants
#define B_   2048
#define MND  128
#define D_   512
#define H_   512
#define KF   2048    // GEMM K = 4*512
#define CHROWS 512   // batch chunk rows for means/gemm overlap
#define NCH    4

// Scratch (device globals; no allocations allowed)
__device__ float g_X[(size_t)B_ * KF];     // [2048,2048] = [img_mean|txt_mean|it|ii]
__device__ float g_Wbig[(size_t)H_ * KF];  // [512,2048]  = [W_l_img|W_l_txt|Wc]
__device__ float g_Wrc[H_ * H_];           // W_r_img + W_r_txt
__device__ float g_bc[H_];                 // combined bias

// ---------------------------------------------------------------------------
// prep: Wbig[:,0:512]=W_l_img, Wbig[:,512:1024]=W_l_txt, Wrc = sum  (exact)
// ---------------------------------------------------------------------------
__global__ void prep_kernel(const float* __restrict__ Wl_img,
                            const float* __restrict__ Wl_txt,
                            const float* __restrict__ Wr_img,
                            const float* __restrict__ Wr_txt) {
    int idx = blockIdx.x * blockDim.x + threadIdx.x;
    if (idx < H_ * 1024) {
        int h = idx >> 10, c = idx & 1023;
        g_Wbig[h * KF + c] = (c < 512) ? Wl_img[h * 512 + c]
                                       : Wl_txt[h * 512 + (c - 512)];
    }
    if (idx < H_ * H_) g_Wrc[idx] = Wr_img[idx] + Wr_txt[idx];
}

// ---------------------------------------------------------------------------
// Wc = Wrc @ W_user  (512x1024x512), exact fp32 -> Wbig cols [1024,2048)
// ---------------------------------------------------------------------------
__global__ void gemm_nn_wc(const float* __restrict__ Wuser) {
    __shared__ float As[16][68];
    __shared__ float Bs[16][68];
    const int bn = blockIdx.x, bm = blockIdx.y, tid = threadIdx.x;
    const int tn = tid & 15, tm = tid >> 4;
    const int ar = tid >> 2, akv = tid & 3;
    const int brow = tid >> 4, bc4 = tid & 15;

    const float* Ap = g_Wrc + (size_t)(bm * 64 + ar) * 512 + akv * 4;
    const float* Bp = Wuser + (size_t)brow * 1024 + bn * 64 + bc4 * 4;

    float acc[4][4] = {};
    for (int k0 = 0; k0 < 512; k0 += 16) {
        float4 av = *(const float4*)(Ap + k0);
        float4 bv = *(const float4*)(Bp + (size_t)k0 * 1024);
        __syncthreads();
        As[akv*4+0][ar]=av.x; As[akv*4+1][ar]=av.y; As[akv*4+2][ar]=av.z; As[akv*4+3][ar]=av.w;
        *(float4*)&Bs[brow][bc4 * 4] = bv;
        __syncthreads();
        #pragma unroll
        for (int k = 0; k < 16; k++) {
            float4 a = *(const float4*)&As[k][tm * 4];
            float4 b = *(const float4*)&Bs[k][tn * 4];
            acc[0][0]+=a.x*b.x; acc[0][1]+=a.x*b.y; acc[0][2]+=a.x*b.z; acc[0][3]+=a.x*b.w;
            acc[1][0]+=a.y*b.x; acc[1][1]+=a.y*b.y; acc[1][2]+=a.y*b.z; acc[1][3]+=a.y*b.w;
            acc[2][0]+=a.z*b.x; acc[2][1]+=a.z*b.y; acc[2][2]+=a.z*b.z; acc[2][3]+=a.z*b.w;
            acc[3][0]+=a.w*b.x; acc[3][1]+=a.w*b.y; acc[3][2]+=a.w*b.z; acc[3][3]+=a.w*b.w;
        }
    }
    int row = bm * 64 + tm * 4, col = bn * 64 + tn * 4;
    #pragma unroll
    for (int i = 0; i < 4; i++)
        *(float4*)&g_Wbig[(size_t)(row + i) * KF + 1024 + col] =
            make_float4(acc[i][0], acc[i][1], acc[i][2], acc[i][3]);
}

// ---------------------------------------------------------------------------
// bc[h] = b_l_img[h] + b_l_txt[h] + sum_k Wrc[h,k] * b_user[k]   (exact)
// ---------------------------------------------------------------------------
__global__ void bc_kernel(const float* __restrict__ b_user,
                          const float* __restrict__ bl_img,
                          const float* __restrict__ bl_txt) {
    int h = blockIdx.x, t = threadIdx.x;
    float s = 0.0f;
    for (int k = t; k < H_; k += 128) s += g_Wrc[h * H_ + k] * b_user[k];
    __shared__ float red[4];
    #pragma unroll
    for (int o = 16; o; o >>= 1) s += __shfl_down_sync(0xffffffffu, s, o);
    if ((t & 31) == 0) red[t >> 5] = s;
    __syncthreads();
    if (t == 0) g_bc[h] = red[0] + red[1] + red[2] + red[3] + bl_img[h] + bl_txt[h];
}

// ---------------------------------------------------------------------------
// means chunk: for b in [b0, b0+CHROWS):
//   X[b] = [mean img | mean txt | it | ii]   (exact fp32; HBM-bound)
// ---------------------------------------------------------------------------
__global__ void means_kernel(const float* __restrict__ img,
                             const float* __restrict__ txt,
                             const float* __restrict__ it,
                             const float* __restrict__ ii,
                             int b0) {
    int b = b0 + blockIdx.x;
    int t = threadIdx.x;
    int h4 = t & 127;
    const bool isimg = (t < 128);
    const float* src = isimg ? img : txt;
    const float4* base = (const float4*)(src + (size_t)b * MND * H_) + h4;

    float4 acc = make_float4(0.f, 0.f, 0.f, 0.f);
    #pragma unroll 16
    for (int m = 0; m < MND; m++) {
        float4 v = base[(size_t)m * (H_ / 4)];
        acc.x += v.x; acc.y += v.y; acc.z += v.z; acc.w += v.w;
    }
    const float inv = 1.0f / (float)MND;
    acc.x *= inv; acc.y *= inv; acc.z *= inv; acc.w *= inv;

    float4* xrow = (float4*)(g_X + (size_t)b * KF);
    xrow[(isimg ? 0 : 128) + h4] = acc;

    const float4* cs = (const float4*)((isimg ? it : ii) + (size_t)b * D_);
    xrow[(isimg ? 256 : 384) + h4] = cs[h4];
}

// ---------------------------------------------------------------------------
// out chunk = relu( X @ Wbig^T + bc ) via packed fp32x2 FFMA (exact fp32).
// 64x64 CTA tile, 256 threads, 4x4 per thread (as 4x2 f32x2 pairs).
// As2 stores A values DUPLICATED ({a,a} pairs) so one LDS.128 yields two
// packed broadcast operands; Bs pairs are naturally consecutive.
// ---------------------------------------------------------------------------
__global__ __launch_bounds__(256) void gemm_out_f2(float* __restrict__ C, int rowoff) {
    __shared__ float As2[16][132];   // duplicated: As2[k][2m]=As2[k][2m+1]=A[m][k]
    __shared__ float Bs[16][68];
    const int bn = blockIdx.x;                 // col tile
    const int bm = blockIdx.y;                 // row tile within chunk
    const int tid = threadIdx.x;
    const int tn = tid & 15, tm = tid >> 4;
    const int ar = tid >> 2, akv = tid & 3;

    const int bm0 = rowoff + bm * 64;
    const float* Ap = g_X    + (size_t)(bm0 + ar) * KF + akv * 4;
    const float* Bp = g_Wbig + (size_t)(blockIdx.x * 64 + ar) * KF + akv * 4;

    unsigned long long acc[4][2];
    #pragma unroll
    for (int i = 0; i < 4; i++) { acc[i][0] = 0ull; acc[i][1] = 0ull; }

    for (int k0 = 0; k0 < KF; k0 += 16) {
        float4 av = *(const float4*)(Ap + k0);
        float4 bv = *(const float4*)(Bp + k0);
        __syncthreads();
        // duplicated A scatter (transposed), plain B scatter
        *(float2*)&As2[akv*4+0][2*ar] = make_float2(av.x, av.x);
        *(float2*)&As2[akv*4+1][2*ar] = make_float2(av.y, av.y);
        *(float2*)&As2[akv*4+2][2*ar] = make_float2(av.z, av.z);
        *(float2*)&As2[akv*4+3][2*ar] = make_float2(av.w, av.w);
        Bs[akv*4+0][ar]=bv.x; Bs[akv*4+1][ar]=bv.y;
        Bs[akv*4+2][ar]=bv.z; Bs[akv*4+3][ar]=bv.w;
        __syncthreads();
        #pragma unroll
        for (int k = 0; k < 16; k++) {
            // 4 duplicated a-pairs (2x LDS.128), 2 b-pairs (1x LDS.128)
            const unsigned long long* ap =
                (const unsigned long long*)&As2[k][tm * 8];
            unsigned long long pa0 = ap[0], pa1 = ap[1], pa2 = ap[2], pa3 = ap[3];
            const unsigned long long* bp =
                (const unsigned long long*)&Bs[k][tn * 4];
            unsigned long long pb0 = bp[0], pb1 = bp[1];
            asm("fma.rn.f32x2 %0, %1, %2, %0;" : "+l"(acc[0][0]) : "l"(pa0), "l"(pb0));
            asm("fma.rn.f32x2 %0, %1, %2, %0;" : "+l"(acc[0][1]) : "l"(pa0), "l"(pb1));
            asm("fma.rn.f32x2 %0, %1, %2, %0;" : "+l"(acc[1][0]) : "l"(pa1), "l"(pb0));
            asm("fma.rn.f32x2 %0, %1, %2, %0;" : "+l"(acc[1][1]) : "l"(pa1), "l"(pb1));
            asm("fma.rn.f32x2 %0, %1, %2, %0;" : "+l"(acc[2][0]) : "l"(pa2), "l"(pb0));
            asm("fma.rn.f32x2 %0, %1, %2, %0;" : "+l"(acc[2][1]) : "l"(pa2), "l"(pb1));
            asm("fma.rn.f32x2 %0, %1, %2, %0;" : "+l"(acc[3][0]) : "l"(pa3), "l"(pb0));
            asm("fma.rn.f32x2 %0, %1, %2, %0;" : "+l"(acc[3][1]) : "l"(pa3), "l"(pb1));
        }
    }

    const int row = bm0 + tm * 4;
    const int col = bn * 64 + tn * 4;
    float4 bias = *(const float4*)&g_bc[col];
    #pragma unroll
    for (int i = 0; i < 4; i++) {
        float2 lo = *(float2*)&acc[i][0];
        float2 hi = *(float2*)&acc[i][1];
        float4 v;
        v.x = fmaxf(lo.x + bias.x, 0.f);
        v.y = fmaxf(lo.y + bias.y, 0.f);
        v.z = fmaxf(hi.x + bias.z, 0.f);
        v.w = fmaxf(hi.y + bias.w, 0.f);
        *(float4*)&C[(size_t)(row + i) * H_ + col] = v;
    }
}

// ---------------------------------------------------------------------------
extern "C" void kernel_launch(void* const* d_in, const int* in_sizes, int n_in,
                              void* d_out, int out_size) {
    const float* it      = (const float*)d_in[0];
    const float* ii      = (const float*)d_in[1];
    const float* txt     = (const float*)d_in[2];
    const float* img     = (const float*)d_in[3];
    const float* W_user  = (const float*)d_in[4];
    const float* b_user  = (const float*)d_in[5];
    const float* Wl_img  = (const float*)d_in[6];
    const float* bl_img  = (const float*)d_in[7];
    const float* Wr_img  = (const float*)d_in[8];
    const float* Wl_txt  = (const float*)d_in[9];
    const float* bl_txt  = (const float*)d_in[10];
    const float* Wr_txt  = (const float*)d_in[11];
    float* out = (float*)d_out;

    cudaStream_t s2;
    cudaEvent_t eFork, eJoin, evM[NCH];
    cudaStreamCreateWithFlags(&s2, cudaStreamNonBlocking);
    cudaEventCreateWithFlags(&eFork, cudaEventDisableTiming);
    cudaEventCreateWithFlags(&eJoin, cudaEventDisableTiming);
    for (int c = 0; c < NCH; c++)
        cudaEventCreateWithFlags(&evM[c], cudaEventDisableTiming);

    cudaEventRecord(eFork, 0);
    cudaStreamWaitEvent(s2, eFork, 0);

    // side stream: weight-prep chain (hidden under means chunk 0)
    prep_kernel<<<2048, 256, 0, s2>>>(Wl_img, Wl_txt, Wr_img, Wr_txt);
    {
        dim3 grid(1024 / 64, 512 / 64);
        gemm_nn_wc<<<grid, 256, 0, s2>>>(W_user);
    }
    bc_kernel<<<512, 128, 0, s2>>>(b_user, bl_img, bl_txt);

    // chunked means (stream 0) -> gemm (stream s2) pipeline
    for (int c = 0; c < NCH; c++) {
        means_kernel<<<CHROWS, 256>>>(img, txt, it, ii, c * CHROWS);
        cudaEventRecord(evM[c], 0);
        cudaStreamWaitEvent(s2, evM[c], 0);
        dim3 grid(H_ / 64, CHROWS / 64);   // (8, 8) = 64 CTAs per chunk
        gemm_out_f2<<<grid, 256, 0, s2>>>(out, c * CHROWS);
    }

    cudaEventRecord(eJoin, s2);
    cudaStreamWaitEvent(0, eJoin, 0);
}

// round 7
// speedup vs baseline: 1.6654x; 1.6654x over previous
#include <cuda_runtime.h>
#include <cstdint>

// Problem constants
#define B_   2048
#define MND  128
#define D_   512
#define H_   512
#define KF   2048    // GEMM K = 4*512
#define CHROWS 512   // batch chunk rows
#define NCH    4
#define KHALF  1024  // K split

// Scratch (device globals; no allocations allowed)
__device__ float g_X[(size_t)B_ * KF];     // [2048,2048] = [img_mean|txt_mean|it|ii]
__device__ float g_Wbig[(size_t)H_ * KF];  // [512,2048]  = [W_l_img|W_l_txt|Wc]
__device__ float g_Wrc[H_ * H_];           // W_r_img + W_r_txt
__device__ float g_bc[H_];                 // combined bias
__device__ float g_p0[(size_t)B_ * H_];    // K-half-0 partials
__device__ float g_p1[(size_t)B_ * H_];    // K-half-1 partials

// ---------------------------------------------------------------------------
// prep: Wbig[:,0:512]=W_l_img, Wbig[:,512:1024]=W_l_txt, Wrc = sum  (exact)
// ---------------------------------------------------------------------------
__global__ void prep_kernel(const float* __restrict__ Wl_img,
                            const float* __restrict__ Wl_txt,
                            const float* __restrict__ Wr_img,
                            const float* __restrict__ Wr_txt) {
    int idx = blockIdx.x * blockDim.x + threadIdx.x;
    if (idx < H_ * 1024) {
        int h = idx >> 10, c = idx & 1023;
        g_Wbig[h * KF + c] = (c < 512) ? Wl_img[h * 512 + c]
                                       : Wl_txt[h * 512 + (c - 512)];
    }
    if (idx < H_ * H_) g_Wrc[idx] = Wr_img[idx] + Wr_txt[idx];
}

// ---------------------------------------------------------------------------
// Wc = Wrc @ W_user  (512x1024x512), exact fp32 -> Wbig cols [1024,2048)
// ---------------------------------------------------------------------------
__global__ void gemm_nn_wc(const float* __restrict__ Wuser) {
    __shared__ float As[16][68];
    __shared__ float Bs[16][68];
    const int bn = blockIdx.x, bm = blockIdx.y, tid = threadIdx.x;
    const int tn = tid & 15, tm = tid >> 4;
    const int ar = tid >> 2, akv = tid & 3;
    const int brow = tid >> 4, bc4 = tid & 15;

    const float* Ap = g_Wrc + (size_t)(bm * 64 + ar) * 512 + akv * 4;
    const float* Bp = Wuser + (size_t)brow * 1024 + bn * 64 + bc4 * 4;

    float acc[4][4] = {};
    for (int k0 = 0; k0 < 512; k0 += 16) {
        float4 av = *(const float4*)(Ap + k0);
        float4 bv = *(const float4*)(Bp + (size_t)k0 * 1024);
        __syncthreads();
        As[akv*4+0][ar]=av.x; As[akv*4+1][ar]=av.y; As[akv*4+2][ar]=av.z; As[akv*4+3][ar]=av.w;
        *(float4*)&Bs[brow][bc4 * 4] = bv;
        __syncthreads();
        #pragma unroll
        for (int k = 0; k < 16; k++) {
            float4 a = *(const float4*)&As[k][tm * 4];
            float4 b = *(const float4*)&Bs[k][tn * 4];
            acc[0][0]+=a.x*b.x; acc[0][1]+=a.x*b.y; acc[0][2]+=a.x*b.z; acc[0][3]+=a.x*b.w;
            acc[1][0]+=a.y*b.x; acc[1][1]+=a.y*b.y; acc[1][2]+=a.y*b.z; acc[1][3]+=a.y*b.w;
            acc[2][0]+=a.z*b.x; acc[2][1]+=a.z*b.y; acc[2][2]+=a.z*b.z; acc[2][3]+=a.z*b.w;
            acc[3][0]+=a.w*b.x; acc[3][1]+=a.w*b.y; acc[3][2]+=a.w*b.z; acc[3][3]+=a.w*b.w;
        }
    }
    int row = bm * 64 + tm * 4, col = bn * 64 + tn * 4;
    #pragma unroll
    for (int i = 0; i < 4; i++)
        *(float4*)&g_Wbig[(size_t)(row + i) * KF + 1024 + col] =
            make_float4(acc[i][0], acc[i][1], acc[i][2], acc[i][3]);
}

// ---------------------------------------------------------------------------
// bc[h] = b_l_img[h] + b_l_txt[h] + sum_k Wrc[h,k] * b_user[k]   (exact)
// ---------------------------------------------------------------------------
__global__ void bc_kernel(const float* __restrict__ b_user,
                          const float* __restrict__ bl_img,
                          const float* __restrict__ bl_txt) {
    int h = blockIdx.x, t = threadIdx.x;
    float s = 0.0f;
    for (int k = t; k < H_; k += 128) s += g_Wrc[h * H_ + k] * b_user[k];
    __shared__ float red[4];
    #pragma unroll
    for (int o = 16; o; o >>= 1) s += __shfl_down_sync(0xffffffffu, s, o);
    if ((t & 31) == 0) red[t >> 5] = s;
    __syncthreads();
    if (t == 0) g_bc[h] = red[0] + red[1] + red[2] + red[3] + bl_img[h] + bl_txt[h];
}

// ---------------------------------------------------------------------------
// means chunk: X[b] = [mean img | mean txt | it | ii]  (exact; HBM-bound)
// ---------------------------------------------------------------------------
__global__ void means_kernel(const float* __restrict__ img,
                             const float* __restrict__ txt,
                             const float* __restrict__ it,
                             const float* __restrict__ ii,
                             int b0) {
    int b = b0 + blockIdx.x;
    int t = threadIdx.x;
    int h4 = t & 127;
    const bool isimg = (t < 128);
    const float* src = isimg ? img : txt;
    const float4* base = (const float4*)(src + (size_t)b * MND * H_) + h4;

    float4 acc = make_float4(0.f, 0.f, 0.f, 0.f);
    #pragma unroll 16
    for (int m = 0; m < MND; m++) {
        float4 v = base[(size_t)m * (H_ / 4)];
        acc.x += v.x; acc.y += v.y; acc.z += v.z; acc.w += v.w;
    }
    const float inv = 1.0f / (float)MND;
    acc.x *= inv; acc.y *= inv; acc.z *= inv; acc.w *= inv;

    float4* xrow = (float4*)(g_X + (size_t)b * KF);
    xrow[(isimg ? 0 : 128) + h4] = acc;

    const float4* cs = (const float4*)((isimg ? it : ii) + (size_t)b * D_);
    xrow[(isimg ? 256 : 384) + h4] = cs[h4];
}

// ---------------------------------------------------------------------------
// Partial GEMM (proven R1 structure): for K-half kh = blockIdx.z,
//   p[kh][row, col] = sum_{k in half} X[row,k] * Wbig[col,k]
// 64x64 tile, 256 threads, 4x4/thread; NT layout; exact fp32.
// Two separate partial buffers -> fully deterministic (no atomics).
// ---------------------------------------------------------------------------
__global__ __launch_bounds__(256) void gemm_part(int rowoff) {
    __shared__ float As[16][68];
    __shared__ float Bs[16][68];
    const int bn = blockIdx.x;                 // 0..7 (col tile)
    const int bm = blockIdx.y;                 // 0..7 (row tile in chunk)
    const int kh = blockIdx.z;                 // 0..1 (K half)
    const int tid = threadIdx.x;
    const int tn = tid & 15, tm = tid >> 4;
    const int ar = tid >> 2, akv = tid & 3;

    const int bm0 = rowoff + bm * 64;
    const int kb  = kh * KHALF;
    const float* Ap = g_X    + (size_t)(bm0 + ar) * KF + kb + akv * 4;
    const float* Bp = g_Wbig + (size_t)(bn * 64 + ar) * KF + kb + akv * 4;

    float acc[4][4] = {};
    for (int k0 = 0; k0 < KHALF; k0 += 16) {
        float4 av = *(const float4*)(Ap + k0);
        float4 bv = *(const float4*)(Bp + k0);
        __syncthreads();
        As[akv*4+0][ar]=av.x; As[akv*4+1][ar]=av.y; As[akv*4+2][ar]=av.z; As[akv*4+3][ar]=av.w;
        Bs[akv*4+0][ar]=bv.x; Bs[akv*4+1][ar]=bv.y; Bs[akv*4+2][ar]=bv.z; Bs[akv*4+3][ar]=bv.w;
        __syncthreads();
        #pragma unroll
        for (int k = 0; k < 16; k++) {
            float4 a = *(const float4*)&As[k][tm * 4];
            float4 b = *(const float4*)&Bs[k][tn * 4];
            acc[0][0]+=a.x*b.x; acc[0][1]+=a.x*b.y; acc[0][2]+=a.x*b.z; acc[0][3]+=a.x*b.w;
            acc[1][0]+=a.y*b.x; acc[1][1]+=a.y*b.y; acc[1][2]+=a.y*b.z; acc[1][3]+=a.y*b.w;
            acc[2][0]+=a.z*b.x; acc[2][1]+=a.z*b.y; acc[2][2]+=a.z*b.z; acc[2][3]+=a.z*b.w;
            acc[3][0]+=a.w*b.x; acc[3][1]+=a.w*b.y; acc[3][2]+=a.w*b.z; acc[3][3]+=a.w*b.w;
        }
    }

    float* P = kh ? g_p1 : g_p0;
    const int row = bm0 + tm * 4;
    const int col = bn * 64 + tn * 4;
    #pragma unroll
    for (int i = 0; i < 4; i++)
        *(float4*)&P[(size_t)(row + i) * H_ + col] =
            make_float4(acc[i][0], acc[i][1], acc[i][2], acc[i][3]);
}

// ---------------------------------------------------------------------------
// epilogue chunk: out[b,:] = relu(p0 + p1 + bc)   (elementwise, ~1 us)
// ---------------------------------------------------------------------------
__global__ void epi_kernel(float* __restrict__ out, int rowoff) {
    int b = rowoff + blockIdx.x;
    int t = threadIdx.x;                       // 128 threads -> 128 float4
    size_t o = (size_t)b * H_ + t * 4;
    float4 a = *(const float4*)&g_p0[o];
    float4 c = *(const float4*)&g_p1[o];
    float4 bias = *(const float4*)&g_bc[t * 4];
    float4 v;
    v.x = fmaxf(a.x + c.x + bias.x, 0.f);
    v.y = fmaxf(a.y + c.y + bias.y, 0.f);
    v.z = fmaxf(a.z + c.z + bias.z, 0.f);
    v.w = fmaxf(a.w + c.w + bias.w, 0.f);
    *(float4*)&out[o] = v;
}

// ---------------------------------------------------------------------------
extern "C" void kernel_launch(void* const* d_in, const int* in_sizes, int n_in,
                              void* d_out, int out_size) {
    const float* it      = (const float*)d_in[0];
    const float* ii      = (const float*)d_in[1];
    const float* txt     = (const float*)d_in[2];
    const float* img     = (const float*)d_in[3];
    const float* W_user  = (const float*)d_in[4];
    const float* b_user  = (const float*)d_in[5];
    const float* Wl_img  = (const float*)d_in[6];
    const float* bl_img  = (const float*)d_in[7];
    const float* Wr_img  = (const float*)d_in[8];
    const float* Wl_txt  = (const float*)d_in[9];
    const float* bl_txt  = (const float*)d_in[10];
    const float* Wr_txt  = (const float*)d_in[11];
    float* out = (float*)d_out;

    cudaStream_t s2;
    cudaEvent_t eFork, eJoin, evM[NCH];
    cudaStreamCreateWithFlags(&s2, cudaStreamNonBlocking);
    cudaEventCreateWithFlags(&eFork, cudaEventDisableTiming);
    cudaEventCreateWithFlags(&eJoin, cudaEventDisableTiming);
    for (int c = 0; c < NCH; c++)
        cudaEventCreateWithFlags(&evM[c], cudaEventDisableTiming);

    cudaEventRecord(eFork, 0);
    cudaStreamWaitEvent(s2, eFork, 0);

    // side stream: weight-prep chain (hidden under means chunk 0)
    prep_kernel<<<2048, 256, 0, s2>>>(Wl_img, Wl_txt, Wr_img, Wr_txt);
    {
        dim3 grid(1024 / 64, 512 / 64);
        gemm_nn_wc<<<grid, 256, 0, s2>>>(W_user);
    }
    bc_kernel<<<512, 128, 0, s2>>>(b_user, bl_img, bl_txt);

    // chunked pipeline: means (s0) -> partial gemms + epilogue (s2)
    for (int c = 0; c < NCH; c++) {
        means_kernel<<<CHROWS, 256>>>(img, txt, it, ii, c * CHROWS);
        cudaEventRecord(evM[c], 0);
        cudaStreamWaitEvent(s2, evM[c], 0);
        dim3 grid(H_ / 64, CHROWS / 64, 2);    // 8 x 8 x 2 = 128 CTAs
        gemm_part<<<grid, 256, 0, s2>>>(c * CHROWS);
        epi_kernel<<<CHROWS, 128, 0, s2>>>(out, c * CHROWS);
    }

    cudaEventRecord(eJoin, s2);
    cudaStreamWaitEvent(0, eJoin, 0);
}

// round 9
// speedup vs baseline: 2.0511x; 1.2316x over previous
#include <cuda_runtime.h>
#include <cstdint>

// Problem constants
#define B_   2048
#define MND  128
#define D_   512
#define H_   512
#define KF   2048    // GEMM K = 4*512
#define CHROWS 512   // pipeline chunk rows
#define KSEG  512    // K per gemm CTA (split x4)
#define NKH   4

// Scratch (device globals; no allocations allowed)
__device__ float g_X[(size_t)B_ * KF];               // [2048,2048]
__device__ float g_Wbig[(size_t)H_ * KF];            // [512,2048]
__device__ float g_bc[H_];                           // combined bias
__device__ float g_part[NKH][(size_t)B_ * H_];       // K-split partials (16MB)

// ===========================================================================
// Mega-kernel: heterogeneous roles selected by blockIdx.x range.
//   [0, gemmCnt)                      : 64x64 K-segment GEMM tiles (chunk at gemmRow)
//   [gemmCnt, +meansCnt)              : means blocks (chunk at meansRow)
//   [.., +epiCnt)                     : epilogue blocks (2 rows each, at epiRow)
//   if setup: [.., +128) wc, [.., +256) prep-copy, [.., +512) bc
// All roles use 256 threads. Roles never share a block -> __syncthreads safe.
// ===========================================================================
__global__ __launch_bounds__(256) void mega_kernel(
    const float* __restrict__ img,    const float* __restrict__ txt,
    const float* __restrict__ it,     const float* __restrict__ ii,
    const float* __restrict__ Wl_img, const float* __restrict__ Wl_txt,
    const float* __restrict__ Wr_img, const float* __restrict__ Wr_txt,
    const float* __restrict__ Wuser,  const float* __restrict__ b_user,
    const float* __restrict__ bl_img, const float* __restrict__ bl_txt,
    float* __restrict__ out,
    int gemmCnt, int gemmRow, int meansCnt, int meansRow,
    int epiCnt, int epiRow, int setup)
{
    __shared__ float As[16][68];
    __shared__ float Bs[16][68];
    __shared__ float red8[8];

    const int tid = threadIdx.x;
    int bid = blockIdx.x;

    // ---------------- GEMM role: partial[kh] = X[rows,kseg] @ Wbig[:,kseg]^T
    if (bid < gemmCnt) {
        const int bn  = bid & 7;          // col tile (512/64)
        const int bmq = (bid >> 3) & 7;   // row tile (512/64)
        const int kh  = bid >> 6;         // K segment 0..3
        const int tn = tid & 15, tm = tid >> 4;
        const int ar = tid >> 2, akv = tid & 3;

        const int row0 = gemmRow + bmq * 64;
        const int kb   = kh * KSEG;
        const float* Ap = g_X    + (size_t)(row0 + ar) * KF + kb + akv * 4;
        const float* Bp = g_Wbig + (size_t)(bn * 64 + ar) * KF + kb + akv * 4;

        float acc[4][4] = {};
        for (int k0 = 0; k0 < KSEG; k0 += 16) {
            float4 av = *(const float4*)(Ap + k0);
            float4 bv = *(const float4*)(Bp + k0);
            __syncthreads();
            As[akv*4+0][ar]=av.x; As[akv*4+1][ar]=av.y;
            As[akv*4+2][ar]=av.z; As[akv*4+3][ar]=av.w;
            Bs[akv*4+0][ar]=bv.x; Bs[akv*4+1][ar]=bv.y;
            Bs[akv*4+2][ar]=bv.z; Bs[akv*4+3][ar]=bv.w;
            __syncthreads();
            #pragma unroll
            for (int k = 0; k < 16; k++) {
                float4 a = *(const float4*)&As[k][tm * 4];
                float4 b = *(const float4*)&Bs[k][tn * 4];
                acc[0][0]+=a.x*b.x; acc[0][1]+=a.x*b.y; acc[0][2]+=a.x*b.z; acc[0][3]+=a.x*b.w;
                acc[1][0]+=a.y*b.x; acc[1][1]+=a.y*b.y; acc[1][2]+=a.y*b.z; acc[1][3]+=a.y*b.w;
                acc[2][0]+=a.z*b.x; acc[2][1]+=a.z*b.y; acc[2][2]+=a.z*b.z; acc[2][3]+=a.z*b.w;
                acc[3][0]+=a.w*b.x; acc[3][1]+=a.w*b.y; acc[3][2]+=a.w*b.z; acc[3][3]+=a.w*b.w;
            }
        }
        float* P = g_part[kh];
        const int row = row0 + tm * 4;
        const int col = bn * 64 + tn * 4;
        #pragma unroll
        for (int i = 0; i < 4; i++)
            *(float4*)&P[(size_t)(row + i) * H_ + col] =
                make_float4(acc[i][0], acc[i][1], acc[i][2], acc[i][3]);
        return;
    }
    bid -= gemmCnt;

    // ---------------- Means role (DRAM-bound; proven structure)
    if (bid < meansCnt) {
        const int b = meansRow + bid;
        const int h4 = tid & 127;
        const bool isimg = (tid < 128);
        const float* src = isimg ? img : txt;
        const float4* base = (const float4*)(src + (size_t)b * MND * H_) + h4;

        float4 acc = make_float4(0.f, 0.f, 0.f, 0.f);
        #pragma unroll 16
        for (int m = 0; m < MND; m++) {
            float4 v = base[(size_t)m * (H_ / 4)];
            acc.x += v.x; acc.y += v.y; acc.z += v.z; acc.w += v.w;
        }
        const float inv = 1.0f / (float)MND;
        acc.x *= inv; acc.y *= inv; acc.z *= inv; acc.w *= inv;

        float4* xrow = (float4*)(g_X + (size_t)b * KF);
        xrow[(isimg ? 0 : 128) + h4] = acc;

        const float4* cs = (const float4*)((isimg ? it : ii) + (size_t)b * D_);
        xrow[(isimg ? 256 : 384) + h4] = cs[h4];
        return;
    }
    bid -= meansCnt;

    // ---------------- Epilogue role: out = relu(sum of 4 partials + bc)
    if (bid < epiCnt) {
        const int b = epiRow + bid * 2 + (tid >> 7);
        const int c4 = tid & 127;
        const size_t o = (size_t)b * H_ + c4 * 4;
        float4 s0 = *(const float4*)&g_part[0][o];
        float4 s1 = *(const float4*)&g_part[1][o];
        float4 s2 = *(const float4*)&g_part[2][o];
        float4 s3 = *(const float4*)&g_part[3][o];
        float4 bias = *(const float4*)&g_bc[c4 * 4];
        float4 v;
        v.x = fmaxf(s0.x + s1.x + s2.x + s3.x + bias.x, 0.f);
        v.y = fmaxf(s0.y + s1.y + s2.y + s3.y + bias.y, 0.f);
        v.z = fmaxf(s0.z + s1.z + s2.z + s3.z + bias.z, 0.f);
        v.w = fmaxf(s0.w + s1.w + s2.w + s3.w + bias.w, 0.f);
        *(float4*)&out[o] = v;
        return;
    }
    bid -= epiCnt;

    if (!setup) return;

    // ---------------- wc role (128 blocks): Wbig[:,1024:2048) = (Wr_img+Wr_txt) @ W_user
    if (bid < 128) {
        const int bn = bid & 15;          // 1024/64
        const int bm = bid >> 4;          // 512/64
        const int tn = tid & 15, tm = tid >> 4;
        const int ar = tid >> 2, akv = tid & 3;
        const int brow = tid >> 4, bc4 = tid & 15;

        const size_t aoff = (size_t)(bm * 64 + ar) * 512 + akv * 4;
        const float* Bp = Wuser + (size_t)brow * 1024 + bn * 64 + bc4 * 4;

        float acc[4][4] = {};
        for (int k0 = 0; k0 < 512; k0 += 16) {
            float4 a1 = *(const float4*)(Wr_img + aoff + k0);
            float4 a2 = *(const float4*)(Wr_txt + aoff + k0);
            float4 av = make_float4(a1.x + a2.x, a1.y + a2.y, a1.z + a2.z, a1.w + a2.w);
            float4 bv = *(const float4*)(Bp + (size_t)k0 * 1024);
            __syncthreads();
            As[akv*4+0][ar]=av.x; As[akv*4+1][ar]=av.y;
            As[akv*4+2][ar]=av.z; As[akv*4+3][ar]=av.w;
            *(float4*)&Bs[brow][bc4 * 4] = bv;
            __syncthreads();
            #pragma unroll
            for (int k = 0; k < 16; k++) {
                float4 a = *(const float4*)&As[k][tm * 4];
                float4 b = *(const float4*)&Bs[k][tn * 4];
                acc[0][0]+=a.x*b.x; acc[0][1]+=a.x*b.y; acc[0][2]+=a.x*b.z; acc[0][3]+=a.x*b.w;
                acc[1][0]+=a.y*b.x; acc[1][1]+=a.y*b.y; acc[1][2]+=a.y*b.z; acc[1][3]+=a.y*b.w;
                acc[2][0]+=a.z*b.x; acc[2][1]+=a.z*b.y; acc[2][2]+=a.z*b.z; acc[2][3]+=a.z*b.w;
                acc[3][0]+=a.w*b.x; acc[3][1]+=a.w*b.y; acc[3][2]+=a.w*b.z; acc[3][3]+=a.w*b.w;
            }
        }
        const int row = bm * 64 + tm * 4;
        const int col = bn * 64 + tn * 4;
        #pragma unroll
        for (int i = 0; i < 4; i++)
            *(float4*)&g_Wbig[(size_t)(row + i) * KF + 1024 + col] =
                make_float4(acc[i][0], acc[i][1], acc[i][2], acc[i][3]);
        return;
    }
    bid -= 128;

    // ---------------- prep role (256 blocks): Wbig[:,0:1024) = [Wl_img | Wl_txt]
    if (bid < 256) {
        #pragma unroll
        for (int j = 0; j < 2; j++) {
            int q = bid * 256 + tid + j * 65536;   // float4 index over 512x1024
            int h = q >> 8, c4 = q & 255;
            int c = c4 * 4;
            float4 v = (c < 512)
                ? *(const float4*)(Wl_img + (size_t)h * 512 + c)
                : *(const float4*)(Wl_txt + (size_t)h * 512 + (c - 512));
            *(float4*)&g_Wbig[(size_t)h * KF + c] = v;
        }
        return;
    }
    bid -= 256;

    // ---------------- bc role (512 blocks): bc[h] = bl_img+bl_txt + Wrc_row . b_user
    {
        const int h = bid;
        float s = 0.0f;
        #pragma unroll
        for (int j = 0; j < 2; j++) {
            int k = tid + j * 256;
            s += (Wr_img[(size_t)h * 512 + k] + Wr_txt[(size_t)h * 512 + k]) * b_user[k];
        }
        #pragma unroll
        for (int o = 16; o; o >>= 1) s += __shfl_down_sync(0xffffffffu, s, o);
        if ((tid & 31) == 0) red8[tid >> 5] = s;
        __syncthreads();
        if (tid == 0) {
            float t = 0.f;
            #pragma unroll
            for (int i = 0; i < 8; i++) t += red8[i];
            g_bc[h] = t + bl_img[h] + bl_txt[h];
        }
        return;
    }
}

// ---------------------------------------------------------------------------
extern "C" void kernel_launch(void* const* d_in, const int* in_sizes, int n_in,
                              void* d_out, int out_size) {
    const float* it      = (const float*)d_in[0];
    const float* ii      = (const float*)d_in[1];
    const float* txt     = (const float*)d_in[2];
    const float* img     = (const float*)d_in[3];
    const float* W_user  = (const float*)d_in[4];
    const float* b_user  = (const float*)d_in[5];
    const float* Wl_img  = (const float*)d_in[6];
    const float* bl_img  = (const float*)d_in[7];
    const float* Wr_img  = (const float*)d_in[8];
    const float* Wl_txt  = (const float*)d_in[9];
    const float* bl_txt  = (const float*)d_in[10];
    const float* Wr_txt  = (const float*)d_in[11];
    float* out = (float*)d_out;

    #define MEGA(grid, gc, gr, mc, mr, ec, er, st)                              \
        mega_kernel<<<(grid), 256>>>(img, txt, it, ii, Wl_img, Wl_txt,          \
            Wr_img, Wr_txt, W_user, b_user, bl_img, bl_txt, out,                \
            (gc), (gr), (mc), (mr), (ec), (er), (st))

    // S0: means(c0) + full weight setup (wc 128 + prep 256 + bc 512)
    MEGA(512 + 896,      0, 0,    512, 0,      0, 0,     1);
    // S1: gemm(c0) + means(c1)
    MEGA(256 + 512,    256, 0,    512, 512,    0, 0,     0);
    // S2: gemm(c1) + means(c2) + epi(c0)
    MEGA(256 + 512 + 256, 256, 512,  512, 1024, 256, 0,  0);
    // S3: gemm(c2) + means(c3) + epi(c1)
    MEGA(256 + 512 + 256, 256, 1024, 512, 1536, 256, 512, 0);
    // S4: gemm(c3) + epi(c2)
    MEGA(256 + 256,    256, 1536,   0, 0,    256, 1024,  0);
    // S5: epi(c3)
    MEGA(256,            0, 0,      0, 0,    256, 1536,  0);

    #undef MEGA
}